// round 7
// baseline (speedup 1.0000x reference)
#include <cuda_runtime.h>
#include <math.h>

#define B_     2
#define C_     128
#define HW_    36864
#define N_     73728
#define E_     4
#define HID_   340
#define NCHW_  9437184

typedef unsigned long long u64;

__device__ __forceinline__ u64 fma2(u64 a, u64 b, u64 c) {
    u64 d; asm("fma.rn.f32x2 %0, %1, %2, %3;" : "=l"(d) : "l"(a), "l"(b), "l"(c)); return d;
}
__device__ __forceinline__ u64 dup2(float x) {
    u64 d; asm("mov.b64 %0, {%1, %1};" : "=l"(d) : "f"(x)); return d;
}
__device__ __forceinline__ float2 unpack2(u64 a) {
    float2 r; asm("mov.b64 {%0, %1}, %2;" : "=f"(r.x), "=f"(r.y) : "l"(a)); return r;
}
__device__ __forceinline__ float gelu_exact(float v) {
    return 0.5f * v * (1.0f + erff(v * 0.70710678118654752440f));
}

// ----------------------------- device scratch -----------------------------
__device__ float g_emb[B_ * C_];
__device__ float g_WbT[B_ * C_ * C_];          // [b][c][o]
__device__ float g_ty[(size_t)N_ * C_];        // conv-out tokens [n][c]
__device__ int   g_cnt[E_];
__device__ int   g_tok[E_ * N_];
__device__ float g_gate[E_ * N_];
__device__ int   g_slot[N_ * 2];
__device__ float g_obuf[(size_t)E_ * N_ * C_]; // gated expert outputs per slot

// ----------------------------- K1: channel means -----------------------------
__global__ void k_mean(const float* __restrict__ x) {
    int row = blockIdx.x;                   // b*C + c
    int t = threadIdx.x;
    const float4* xr = (const float4*)(x + (size_t)row * HW_);
    float s = 0.f;
    for (int i = t; i < HW_ / 4; i += 256) {
        float4 v = xr[i];
        s += (v.x + v.y) + (v.z + v.w);
    }
    __shared__ float sm[256];
    sm[t] = s; __syncthreads();
    for (int o = 128; o > 0; o >>= 1) {
        if (t < o) sm[t] += sm[t + o];
        __syncthreads();
    }
    if (t == 0) g_emb[row] = sm[0] * (1.0f / (float)HW_);
}

// --------------------- K2: prompt softmax + fold conv W ---------------------
__global__ void k_prep(const float* __restrict__ prompt, const float* __restrict__ w_lin,
                       const float* __restrict__ b_lin, const float* __restrict__ w_conv) {
    int t = threadIdx.x;
    __shared__ float s_l[B_ * 5], s_pw[B_ * 5], s_sp[B_ * C_];
    if (t < E_) g_cnt[t] = 0;               // reset routing counters every launch
    if (t < B_ * 5) {
        int b = t / 5, p = t % 5;
        float a = b_lin[p];
        for (int c = 0; c < C_; c++) a += g_emb[b * C_ + c] * w_lin[p * C_ + c];
        s_l[t] = a;
    }
    __syncthreads();
    if (t < B_) {
        float m = s_l[t * 5];
        for (int p = 1; p < 5; p++) m = fmaxf(m, s_l[t * 5 + p]);
        float e[5]; float den = 0.f;
        for (int p = 0; p < 5; p++) { e[p] = expf(s_l[t * 5 + p] - m); den += e[p]; }
        for (int p = 0; p < 5; p++) s_pw[t * 5 + p] = e[p] / den;
    }
    __syncthreads();
    {
        int b = t >> 7, c = t & 127;
        float a = 0.f;
        for (int p = 0; p < 5; p++) a += s_pw[b * 5 + p] * prompt[p * C_ + c];
        s_sp[t] = a;
    }
    __syncthreads();
    for (int i = t; i < B_ * C_ * C_; i += 256) {
        int b = i >> 14; int rem = i & 16383; int c = rem >> 7; int o = rem & 127;
        g_WbT[i] = w_conv[o * C_ + c] * s_sp[b * C_ + c];
    }
}

// ---------------- K3: 1x1 conv + gating + top-2 routing scatter ----------------
__global__ void __launch_bounds__(256) k_conv_gate(const float* __restrict__ x,
                                                   const float* __restrict__ w_gate) {
    __shared__ __align__(16) float s_x[C_ * 66];
    __shared__ float s_lg[64 * 4];
    int t = threadIdx.x;
    int n0 = blockIdx.x * 64;
    int b = n0 / HW_; int hw0 = n0 % HW_;
    const float* xb = x + (size_t)b * C_ * HW_ + hw0;
    for (int i = t; i < C_ * 64; i += 256) {
        int c = i >> 6, tk = i & 63;
        s_x[c * 66 + tk] = xb[(size_t)c * HW_ + tk];
    }
    __syncthreads();
    {   // gating logits: thread = (expert, token)
        int e = t >> 6, tk = t & 63;
        float a = 0.f;
        #pragma unroll 8
        for (int c = 0; c < C_; c++) a += s_x[c * 66 + tk] * w_gate[c * 4 + e];
        s_lg[tk * 4 + e] = a;
    }
    __syncthreads();
    if (t < 64) {       // top-2 + softmax + scatter
        float l[4];
        #pragma unroll
        for (int e = 0; e < 4; e++) l[e] = s_lg[t * 4 + e];
        int e0 = 0; float m0 = l[0];
        #pragma unroll
        for (int e = 1; e < 4; e++) if (l[e] > m0) { m0 = l[e]; e0 = e; }
        int e1 = (e0 == 0) ? 1 : 0; float m1 = l[e1];
        #pragma unroll
        for (int e = 0; e < 4; e++) if (e != e0 && l[e] > m1) { m1 = l[e]; e1 = e; }
        float ex = expf(m1 - m0);
        float g0 = 1.0f / (1.0f + ex);
        float g1 = ex * g0;
        int n = n0 + t;
        int p0 = atomicAdd(&g_cnt[e0], 1);
        g_tok[e0 * N_ + p0] = n; g_gate[e0 * N_ + p0] = g0;
        g_slot[n * 2 + 0] = e0 * N_ + p0;
        int p1 = atomicAdd(&g_cnt[e1], 1);
        g_tok[e1 * N_ + p1] = n; g_gate[e1 * N_ + p1] = g1;
        g_slot[n * 2 + 1] = e1 * N_ + p1;
    }
    // conv GEMM: ty[tok][o] = sum_c s_x[c][tok] * WbT[b][c][o]
    // lane owns tokens (2*lane, 2*lane+1); warp owns 16 output cols.
    int warp = t >> 5, lane = t & 31;
    int wcol = warp * 16;
    u64 acc[2][8];
    #pragma unroll
    for (int tt = 0; tt < 2; tt++)
        #pragma unroll
        for (int j = 0; j < 8; j++) acc[tt][j] = 0ull;
    const float* wr = g_WbT + b * C_ * C_ + wcol;
    const float* ap = s_x + lane * 2;
    #pragma unroll 2
    for (int c = 0; c < C_; c++) {
        float2 av = *(const float2*)ap; ap += 66;
        u64 A0 = dup2(av.x), A1 = dup2(av.y);
        #pragma unroll
        for (int q = 0; q < 4; q++) {
            ulonglong2 W = *(const ulonglong2*)(wr + 4 * q);
            acc[0][2*q]   = fma2(A0, W.x, acc[0][2*q]);
            acc[0][2*q+1] = fma2(A0, W.y, acc[0][2*q+1]);
            acc[1][2*q]   = fma2(A1, W.x, acc[1][2*q]);
            acc[1][2*q+1] = fma2(A1, W.y, acc[1][2*q+1]);
        }
        wr += C_;
    }
    #pragma unroll
    for (int tt = 0; tt < 2; tt++) {
        size_t tok = (size_t)(n0 + lane * 2 + tt);
        float* op = g_ty + tok * C_ + wcol;
        #pragma unroll
        for (int k = 0; k < 4; k++) {
            float2 v0 = unpack2(acc[tt][2*k]), v1 = unpack2(acc[tt][2*k+1]);
            *(float4*)(op + 4 * k) = make_float4(v0.x, v0.y, v1.x, v1.y);
        }
    }
}

// ---------------- K4: fused expert fc1 + gelu + fc2 (routed) ----------------
// smem: s_ty[128][66] | s_h[128][66] | s_g[64] | s_tk[64]  => 68,096 B
// Lane owns 2 tokens (LDS.64 distinct); warp owns 16 weight cols (broadcast
// LDG.128, weights arrive pre-packed as f32x2 pairs — no dup needed).
#define SMX_H     8448
#define SMX_G     16896
#define SMX_TK    16960
#define SMX_BYTES (17024 * 4)

__global__ void __launch_bounds__(256, 2) k_expert(const float* __restrict__ w1,
                                                   const float* __restrict__ b1,
                                                   const float* __restrict__ w2,
                                                   const float* __restrict__ b2) {
    extern __shared__ __align__(16) float sm[];
    float* s_ty = sm;
    float* s_h  = sm + SMX_H;
    float* s_g  = sm + SMX_G;
    int*   s_tk = (int*)(sm + SMX_TK);

    int e = blockIdx.y;
    int cnt = g_cnt[e];
    int start = blockIdx.x * 64;
    if (start >= cnt) return;
    int t = threadIdx.x;
    if (t < 64) {
        int idx = start + t;
        if (idx < cnt) { s_tk[t] = g_tok[e * N_ + idx]; s_g[t] = g_gate[e * N_ + idx]; }
        else           { s_tk[t] = 0;                   s_g[t] = 0.f; }
    }
    __syncthreads();
    // gather ty tile, transposed [c][slot]
    #pragma unroll
    for (int k = 0; k < 8; k++) {
        int lin = t + k * 256; int slot = lin >> 5, c4 = lin & 31;
        int tok = s_tk[slot];
        float4 v = *(const float4*)(g_ty + (size_t)tok * C_ + c4 * 4);
        s_ty[(c4 * 4 + 0) * 66 + slot] = v.x;
        s_ty[(c4 * 4 + 1) * 66 + slot] = v.y;
        s_ty[(c4 * 4 + 2) * 66 + slot] = v.z;
        s_ty[(c4 * 4 + 3) * 66 + slot] = v.w;
    }
    int warp = t >> 5, lane = t & 31;
    int wcol = warp * 16;
    const float* w1e = w1 + e * C_ * HID_;
    const float* w2e = w2 + e * HID_ * C_;
    u64 out[2][8];
    #pragma unroll
    for (int tt = 0; tt < 2; tt++)
        #pragma unroll
        for (int j = 0; j < 8; j++) out[tt][j] = 0ull;

    for (int ch = 0; ch < 3; ch++) {
        int hb = ch * 128;
        int qoff[4];
        #pragma unroll
        for (int q = 0; q < 4; q++) {
            int hs = hb + wcol + 4 * q;
            qoff[q] = (hs + 4 <= HID_) ? hs : 0;     // clamp OOB quads (340%4==0)
        }
        __syncthreads();                   // gather done / prev fc2 done with s_h

        // ---- fc1: h[hid][tok] for this chunk ----
        u64 acc[2][8];
        #pragma unroll
        for (int q = 0; q < 4; q++) {
            ulonglong2 Bq = *(const ulonglong2*)(b1 + e * HID_ + qoff[q]);
            acc[0][2*q] = Bq.x; acc[0][2*q+1] = Bq.y;
            acc[1][2*q] = Bq.x; acc[1][2*q+1] = Bq.y;
        }
        {
            const float* ap = s_ty + lane * 2;
            const float* wrow = w1e;
            #pragma unroll 2
            for (int c = 0; c < C_; c++) {
                float2 av = *(const float2*)ap; ap += 66;
                u64 A0 = dup2(av.x), A1 = dup2(av.y);
                #pragma unroll
                for (int q = 0; q < 4; q++) {
                    ulonglong2 W = *(const ulonglong2*)(wrow + qoff[q]);
                    acc[0][2*q]   = fma2(A0, W.x, acc[0][2*q]);
                    acc[0][2*q+1] = fma2(A0, W.y, acc[0][2*q+1]);
                    acc[1][2*q]   = fma2(A1, W.x, acc[1][2*q]);
                    acc[1][2*q+1] = fma2(A1, W.y, acc[1][2*q+1]);
                }
                wrow += HID_;
            }
        }
        // gelu + store h transposed [hid_in_chunk][tok] (rows >= hmax never read)
        #pragma unroll
        for (int tt = 0; tt < 2; tt++)
            #pragma unroll
            for (int j = 0; j < 8; j++) {
                float2 v = unpack2(acc[tt][j]);
                v.x = gelu_exact(v.x); v.y = gelu_exact(v.y);
                s_h[(wcol + 2*j + 0) * 66 + lane * 2 + tt] = v.x;
                s_h[(wcol + 2*j + 1) * 66 + lane * 2 + tt] = v.y;
            }
        __syncthreads();

        // ---- fc2: accumulate out over this chunk's valid hids ----
        int hmax = HID_ - hb; if (hmax > 128) hmax = 128;
        const float* hp = s_h + lane * 2;
        const float* w2row = w2e + hb * C_ + wcol;
        #pragma unroll 2
        for (int hh = 0; hh < hmax; hh++) {
            float2 av = *(const float2*)hp; hp += 66;
            u64 A0 = dup2(av.x), A1 = dup2(av.y);
            #pragma unroll
            for (int q = 0; q < 4; q++) {
                ulonglong2 W = *(const ulonglong2*)(w2row + 4 * q);
                out[0][2*q]   = fma2(A0, W.x, out[0][2*q]);
                out[0][2*q+1] = fma2(A0, W.y, out[0][2*q+1]);
                out[1][2*q]   = fma2(A1, W.x, out[1][2*q]);
                out[1][2*q+1] = fma2(A1, W.y, out[1][2*q+1]);
            }
            w2row += C_;
        }
    }
    // epilogue: gate * (out + b2) -> slot buffer
    float4 b2v[4];
    #pragma unroll
    for (int k = 0; k < 4; k++) b2v[k] = *(const float4*)(b2 + e * C_ + wcol + 4 * k);
    #pragma unroll
    for (int tt = 0; tt < 2; tt++) {
        float g = s_g[lane * 2 + tt];
        size_t slot = (size_t)(e * N_ + start + lane * 2 + tt);
        float* op = g_obuf + slot * C_ + wcol;
        #pragma unroll
        for (int k = 0; k < 4; k++) {
            float2 v0 = unpack2(out[tt][2*k]), v1 = unpack2(out[tt][2*k+1]);
            *(float4*)(op + 4 * k) = make_float4(g * (v0.x + b2v[k].x),
                                                 g * (v0.y + b2v[k].y),
                                                 g * (v1.x + b2v[k].z),
                                                 g * (v1.y + b2v[k].w));
        }
    }
}

// ------------------- K5: combine slots + residual, NCHW -------------------
__global__ void __launch_bounds__(256) k_combine(const float* __restrict__ x,
                                                 float* __restrict__ dout) {
    __shared__ float s_y[C_ * 66];
    __shared__ int s_sl[128];
    int t = threadIdx.x;
    int n0 = blockIdx.x * 64;
    int b = n0 / HW_; int hw0 = n0 % HW_;
    if (t < 128) s_sl[t] = g_slot[n0 * 2 + t];
    __syncthreads();
    #pragma unroll
    for (int k = 0; k < 8; k++) {
        int lin = t + k * 256; int ts = lin >> 5, c4 = lin & 31;
        int s0 = s_sl[ts * 2], s1 = s_sl[ts * 2 + 1];
        float4 a = *(const float4*)(g_obuf + (size_t)s0 * C_ + c4 * 4);
        float4 bb = *(const float4*)(g_obuf + (size_t)s1 * C_ + c4 * 4);
        s_y[(c4 * 4 + 0) * 66 + ts] = a.x + bb.x;
        s_y[(c4 * 4 + 1) * 66 + ts] = a.y + bb.y;
        s_y[(c4 * 4 + 2) * 66 + ts] = a.z + bb.z;
        s_y[(c4 * 4 + 3) * 66 + ts] = a.w + bb.w;
    }
    __syncthreads();
    size_t base = (size_t)b * C_ * HW_ + hw0;
    for (int k = 0; k < 32; k++) {
        int lin = t + k * 256; int c = lin >> 6, tk = lin & 63;
        size_t idx = base + (size_t)c * HW_ + tk;
        dout[idx] = s_y[c * 66 + tk] + x[idx];
    }
}

// ------------------------------- K6: aux loss -------------------------------
__global__ void k_loss(float* __restrict__ dout, int has_loss) {
    __shared__ float s_imp[E_];
    int t = threadIdx.x;
    int e = t >> 5, lane = t & 31;
    if (t < 128) {
        int cnt = g_cnt[e];
        float s = 0.f;
        for (int i = lane; i < cnt; i += 32) s += g_gate[e * N_ + i];
        #pragma unroll
        for (int o = 16; o > 0; o >>= 1) s += __shfl_xor_sync(0xffffffff, s, o);
        if (lane == 0) s_imp[e] = s;
    }
    __syncthreads();
    if (t == 0 && has_loss) {
        float L[E_], I[E_];
        float mi = 0.f, ml = 0.f;
        for (int k = 0; k < E_; k++) {
            I[k] = s_imp[k]; L[k] = (float)g_cnt[k];
            mi += I[k]; ml += L[k];
        }
        mi *= 0.25f; ml *= 0.25f;
        float vi = 0.f, vl = 0.f;
        for (int k = 0; k < E_; k++) {
            float di = I[k] - mi, dl = L[k] - ml;
            vi += di * di; vl += dl * dl;
        }
        vi *= 0.25f; vl *= 0.25f;
        float loss = 1e-2f * (vi / (mi * mi + 1e-10f) + vl / (ml * ml + 1e-10f));
        dout[NCHW_] = loss;
    }
}

// --------------------------------- launcher ---------------------------------
extern "C" void kernel_launch(void* const* d_in, const int* in_sizes, int n_in,
                              void* d_out, int out_size) {
    const float* x      = (const float*)d_in[0];
    const float* prompt = (const float*)d_in[1];
    const float* w_lin  = (const float*)d_in[2];
    const float* b_lin  = (const float*)d_in[3];
    const float* w_conv = (const float*)d_in[4];
    const float* w_gate = (const float*)d_in[5];
    const float* w1     = (const float*)d_in[6];
    const float* b1     = (const float*)d_in[7];
    const float* w2     = (const float*)d_in[8];
    const float* b2     = (const float*)d_in[9];
    float* out = (float*)d_out;

    cudaFuncSetAttribute(k_expert, cudaFuncAttributeMaxDynamicSharedMemorySize, SMX_BYTES);

    k_mean<<<B_ * C_, 256>>>(x);
    k_prep<<<1, 256>>>(prompt, w_lin, b_lin, w_conv);
    k_conv_gate<<<N_ / 64, 256>>>(x, w_gate);
    dim3 ge(N_ / 64, E_);
    k_expert<<<ge, 256, SMX_BYTES>>>(w1, b1, w2, b2);
    k_combine<<<N_ / 64, 256>>>(x, out);
    k_loss<<<1, 128>>>(out, (out_size > NCHW_) ? 1 : 0);
}

// round 8
// speedup vs baseline: 3.1558x; 3.1558x over previous
#include <cuda_runtime.h>
#include <cuda_bf16.h>
#include <math.h>

#define B_     2
#define C_     128
#define HW_    36864
#define N_     73728
#define E_     4
#define HID_   340
#define HIDP_  384
#define NCHW_  9437184

typedef unsigned long long u64;
typedef unsigned int u32;

__device__ __forceinline__ u64 fma2(u64 a, u64 b, u64 c) {
    u64 d; asm("fma.rn.f32x2 %0, %1, %2, %3;" : "=l"(d) : "l"(a), "l"(b), "l"(c)); return d;
}
__device__ __forceinline__ u64 dup2(float x) {
    u64 d; asm("mov.b64 %0, {%1, %1};" : "=l"(d) : "f"(x)); return d;
}
__device__ __forceinline__ float2 unpack2(u64 a) {
    float2 r; asm("mov.b64 {%0, %1}, %2;" : "=f"(r.x), "=f"(r.y) : "l"(a)); return r;
}
__device__ __forceinline__ float gelu_exact(float v) {
    return 0.5f * v * (1.0f + erff(v * 0.70710678118654752440f));
}
// pack {lo, hi} floats -> bf16x2 in one u32 (lo in low 16 bits)
__device__ __forceinline__ u32 pkbf(float lo, float hi) {
    u32 d; asm("cvt.rn.bf16x2.f32 %0, %1, %2;" : "=r"(d) : "f"(hi), "f"(lo)); return d;
}
__device__ __forceinline__ void mma_bf16(float& c0, float& c1, float& c2, float& c3,
                                         u32 a0, u32 a1, u32 a2, u32 a3, u32 b0, u32 b1) {
    asm("mma.sync.aligned.m16n8k16.row.col.f32.bf16.bf16.f32 "
        "{%0,%1,%2,%3}, {%4,%5,%6,%7}, {%8,%9}, {%0,%1,%2,%3};"
        : "+f"(c0), "+f"(c1), "+f"(c2), "+f"(c3)
        : "r"(a0), "r"(a1), "r"(a2), "r"(a3), "r"(b0), "r"(b1));
}

// ----------------------------- device scratch -----------------------------
__device__ float g_emb[B_ * C_];
__device__ float g_WbT[B_ * C_ * C_];          // [b][c][o]
__device__ float g_ty[(size_t)N_ * C_];        // conv-out tokens [n][c]
__device__ int   g_cnt[E_];
__device__ int   g_tok[E_ * N_];
__device__ float g_gate[E_ * N_];
__device__ int   g_slot[N_ * 2];
__device__ float g_obuf[(size_t)E_ * N_ * C_]; // gated expert outputs per slot
// packed bf16 weights in m16n8k16 B-fragment order
__device__ u32   g_w1k[98304];                 // [e][24 pr][8 kt][32 lane][4]
__device__ u32   g_w2k[98304];                 // [e][8 pr][24 kt][32 lane][4]
__device__ float g_b1p[E_ * HIDP_];            // padded b1

// ----------------------------- K1: channel means -----------------------------
__global__ void k_mean(const float* __restrict__ x) {
    int row = blockIdx.x;                   // b*C + c
    int t = threadIdx.x;
    const float4* xr = (const float4*)(x + (size_t)row * HW_);
    float s = 0.f;
    for (int i = t; i < HW_ / 4; i += 256) {
        float4 v = xr[i];
        s += (v.x + v.y) + (v.z + v.w);
    }
    __shared__ float sm[256];
    sm[t] = s; __syncthreads();
    for (int o = 128; o > 0; o >>= 1) {
        if (t < o) sm[t] += sm[t + o];
        __syncthreads();
    }
    if (t == 0) g_emb[row] = sm[0] * (1.0f / (float)HW_);
}

// --------------------- K2: prompt softmax + fold conv W ---------------------
__global__ void k_prep(const float* __restrict__ prompt, const float* __restrict__ w_lin,
                       const float* __restrict__ b_lin, const float* __restrict__ w_conv) {
    int t = threadIdx.x;
    __shared__ float s_l[B_ * 5], s_pw[B_ * 5], s_sp[B_ * C_];
    if (t < E_) g_cnt[t] = 0;               // reset routing counters every launch
    if (t < B_ * 5) {
        int b = t / 5, p = t % 5;
        float a = b_lin[p];
        for (int c = 0; c < C_; c++) a += g_emb[b * C_ + c] * w_lin[p * C_ + c];
        s_l[t] = a;
    }
    __syncthreads();
    if (t < B_) {
        float m = s_l[t * 5];
        for (int p = 1; p < 5; p++) m = fmaxf(m, s_l[t * 5 + p]);
        float e[5]; float den = 0.f;
        for (int p = 0; p < 5; p++) { e[p] = expf(s_l[t * 5 + p] - m); den += e[p]; }
        for (int p = 0; p < 5; p++) s_pw[t * 5 + p] = e[p] / den;
    }
    __syncthreads();
    {
        int b = t >> 7, c = t & 127;
        float a = 0.f;
        for (int p = 0; p < 5; p++) a += s_pw[b * 5 + p] * prompt[p * C_ + c];
        s_sp[t] = a;
    }
    __syncthreads();
    for (int i = t; i < B_ * C_ * C_; i += 256) {
        int b = i >> 14; int rem = i & 16383; int c = rem >> 7; int o = rem & 127;
        g_WbT[i] = w_conv[o * C_ + c] * s_sp[b * C_ + c];
    }
}

// ----------------- K2b: pack expert weights to bf16 fragments -----------------
__global__ void k_pack(const float* __restrict__ w1, const float* __restrict__ b1,
                       const float* __restrict__ w2) {
    int i = blockIdx.x * 256 + threadIdx.x;
    if (i < 98304) {                 // w1k: n8 pairs over HIDP, k over C
        int r = i & 3, lane = (i >> 2) & 31, kt = (i >> 7) & 7;
        int pe = i >> 10; int pr = pe % 24; int e = pe / 24;
        int n = (pr * 2 + (r >> 1)) * 8 + (lane >> 2);
        int k = kt * 16 + (lane & 3) * 2 + (r & 1) * 8;
        float v0 = 0.f, v1 = 0.f;
        if (n < HID_) {
            v0 = w1[((size_t)(e * C_ + k)) * HID_ + n];
            v1 = w1[((size_t)(e * C_ + k + 1)) * HID_ + n];
        }
        g_w1k[i] = pkbf(v0, v1);
    } else if (i < 196608) {         // w2k: n8 pairs over C, k over HIDP
        int j = i - 98304;
        int r = j & 3, lane = (j >> 2) & 31;
        int rest = j >> 7; int kt = rest % 24; int pe = rest / 24;
        int pr = pe & 7; int e = pe >> 3;
        int n = (pr * 2 + (r >> 1)) * 8 + (lane >> 2);
        int k = kt * 16 + (lane & 3) * 2 + (r & 1) * 8;
        float v0 = (k < HID_)     ? w2[((size_t)(e * HID_ + k)) * C_ + n]     : 0.f;
        float v1 = (k + 1 < HID_) ? w2[((size_t)(e * HID_ + k + 1)) * C_ + n] : 0.f;
        g_w2k[j] = pkbf(v0, v1);
    } else if (i < 196608 + E_ * HIDP_) {
        int l = i - 196608; int e = l / HIDP_, n = l % HIDP_;
        g_b1p[l] = (n < HID_) ? b1[e * HID_ + n] : 0.f;
    }
}

// ---------------- K3: 1x1 conv + gating + top-2 routing scatter ----------------
__global__ void __launch_bounds__(256) k_conv_gate(const float* __restrict__ x,
                                                   const float* __restrict__ w_gate) {
    __shared__ __align__(16) float s_x[C_ * 66];
    __shared__ float s_lg[64 * 4];
    int t = threadIdx.x;
    int n0 = blockIdx.x * 64;
    int b = n0 / HW_; int hw0 = n0 % HW_;
    const float* xb = x + (size_t)b * C_ * HW_ + hw0;
    for (int i = t; i < C_ * 64; i += 256) {
        int c = i >> 6, tk = i & 63;
        s_x[c * 66 + tk] = xb[(size_t)c * HW_ + tk];
    }
    __syncthreads();
    {   // gating logits: thread = (expert, token)
        int e = t >> 6, tk = t & 63;
        float a = 0.f;
        #pragma unroll 8
        for (int c = 0; c < C_; c++) a += s_x[c * 66 + tk] * w_gate[c * 4 + e];
        s_lg[tk * 4 + e] = a;
    }
    __syncthreads();
    if (t < 64) {       // top-2 + softmax + scatter
        float l[4];
        #pragma unroll
        for (int e = 0; e < 4; e++) l[e] = s_lg[t * 4 + e];
        int e0 = 0; float m0 = l[0];
        #pragma unroll
        for (int e = 1; e < 4; e++) if (l[e] > m0) { m0 = l[e]; e0 = e; }
        int e1 = (e0 == 0) ? 1 : 0; float m1 = l[e1];
        #pragma unroll
        for (int e = 0; e < 4; e++) if (e != e0 && l[e] > m1) { m1 = l[e]; e1 = e; }
        float ex = expf(m1 - m0);
        float g0 = 1.0f / (1.0f + ex);
        float g1 = ex * g0;
        int n = n0 + t;
        int p0 = atomicAdd(&g_cnt[e0], 1);
        g_tok[e0 * N_ + p0] = n; g_gate[e0 * N_ + p0] = g0;
        g_slot[n * 2 + 0] = e0 * N_ + p0;
        int p1 = atomicAdd(&g_cnt[e1], 1);
        g_tok[e1 * N_ + p1] = n; g_gate[e1 * N_ + p1] = g1;
        g_slot[n * 2 + 1] = e1 * N_ + p1;
    }
    // conv GEMM: ty[tok][o] = sum_c s_x[c][tok] * WbT[b][c][o]
    int warp = t >> 5, lane = t & 31, tokb = warp * 8;
    u64 acc[4][4];
    #pragma unroll
    for (int p = 0; p < 4; p++)
        #pragma unroll
        for (int j = 0; j < 4; j++) acc[p][j] = 0ull;
    const float* wr = g_WbT + b * C_ * C_ + lane * 4;
    #pragma unroll 4
    for (int c = 0; c < C_; c++) {
        float4 w = *(const float4*)(wr + c * C_);
        const u64* ap = (const u64*)(s_x + c * 66 + tokb);
        u64 a[4]; a[0] = ap[0]; a[1] = ap[1]; a[2] = ap[2]; a[3] = ap[3];
        u64 d[4]; d[0] = dup2(w.x); d[1] = dup2(w.y); d[2] = dup2(w.z); d[3] = dup2(w.w);
        #pragma unroll
        for (int p = 0; p < 4; p++)
            #pragma unroll
            for (int j = 0; j < 4; j++) acc[p][j] = fma2(a[p], d[j], acc[p][j]);
    }
    #pragma unroll
    for (int p = 0; p < 4; p++) {
        float2 v0 = unpack2(acc[p][0]), v1 = unpack2(acc[p][1]);
        float2 v2 = unpack2(acc[p][2]), v3 = unpack2(acc[p][3]);
        size_t tok0 = (size_t)(n0 + tokb + 2 * p);
        *(float4*)(g_ty + tok0 * C_ + lane * 4)       = make_float4(v0.x, v1.x, v2.x, v3.x);
        *(float4*)(g_ty + (tok0 + 1) * C_ + lane * 4) = make_float4(v0.y, v1.y, v2.y, v3.y);
    }
}

// ---------------- K4: fused expert fc1 + gelu + fc2 (bf16 HMMA) ----------------
// smem (u32 units): s_a[4*8*32*4]=4096 | s_h[4*24*32*4]=12288 | s_g[64] | s_tk[64]
#define SMU_A   0
#define SMU_H   4096
#define SMU_G   16384
#define SMU_TK  16448
#define SMU_TOT 16512
#define SMX_BYTES (SMU_TOT * 4)

__global__ void __launch_bounds__(256, 2) k_expert(const float* __restrict__ b2) {
    extern __shared__ __align__(16) u32 smu[];
    u32*   s_a  = smu + SMU_A;
    u32*   s_h  = smu + SMU_H;
    float* s_g  = (float*)(smu + SMU_G);
    int*   s_tk = (int*)(smu + SMU_TK);

    int e = blockIdx.y;
    int cnt = g_cnt[e];
    int start = blockIdx.x * 64;
    if (start >= cnt) return;
    int t = threadIdx.x;
    if (t < 64) {
        int idx = start + t;
        if (idx < cnt) { s_tk[t] = g_tok[e * N_ + idx]; s_g[t] = g_gate[e * N_ + idx]; }
        else           { s_tk[t] = 0;                   s_g[t] = 0.f; }
    }
    __syncthreads();
    // gather ty -> bf16 A-fragments in smem
    #pragma unroll
    for (int i = 0; i < 16; i++) {
        int idx = t + i * 256;              // over 64 tokens x 64 col-pairs
        int m = idx >> 6, cp = idx & 63, c = cp * 2;
        int tok = s_tk[m];
        float2 v = *(const float2*)(g_ty + (size_t)tok * C_ + c);
        int mt = m >> 4, mr = m & 15, g = mr & 7, hi = mr >> 3;
        int kt = c >> 4, ko = c & 15, half = ko >> 3, tig = (ko & 7) >> 1;
        int lane = g * 4 + tig, reg = half * 2 + hi;
        s_a[((mt * 8 + kt) * 32 + lane) * 4 + reg] = pkbf(v.x, v.y);
    }
    __syncthreads();

    int warp = t >> 5, lane = t & 31, g = lane >> 2, tig = lane & 3;
    int mt = warp & 3, nh = warp >> 2;

    // ---- fc1: two passes of 12 n8-tiles; output to s_h as fc2 A-fragments ----
    for (int p = 0; p < 2; p++) {
        float acc[12][4];
        #pragma unroll
        for (int j2 = 0; j2 < 12; j2++) {
            int nt = nh * 24 + p * 12 + j2;
            float2 bv = *(const float2*)(g_b1p + e * HIDP_ + nt * 8 + tig * 2);
            acc[j2][0] = bv.x; acc[j2][1] = bv.y; acc[j2][2] = bv.x; acc[j2][3] = bv.y;
        }
        const u32* wbase = g_w1k + (e * 24 + nh * 12 + p * 6) * 1024 + lane * 4;
        #pragma unroll
        for (int kt = 0; kt < 8; kt++) {
            uint4 A = *(const uint4*)(s_a + ((mt * 8 + kt) * 32 + lane) * 4);
            #pragma unroll
            for (int j = 0; j < 6; j++) {
                uint4 Bv = *(const uint4*)(wbase + j * 1024 + kt * 128);
                mma_bf16(acc[2*j][0],   acc[2*j][1],   acc[2*j][2],   acc[2*j][3],
                         A.x, A.y, A.z, A.w, Bv.x, Bv.y);
                mma_bf16(acc[2*j+1][0], acc[2*j+1][1], acc[2*j+1][2], acc[2*j+1][3],
                         A.x, A.y, A.z, A.w, Bv.z, Bv.w);
            }
        }
        #pragma unroll
        for (int j = 0; j < 6; j++) {       // gelu + pack: accum frag pair == fc2 A frag
            int ktg = nh * 12 + p * 6 + j;
            u32 r0 = pkbf(gelu_exact(acc[2*j][0]),   gelu_exact(acc[2*j][1]));
            u32 r1 = pkbf(gelu_exact(acc[2*j][2]),   gelu_exact(acc[2*j][3]));
            u32 r2 = pkbf(gelu_exact(acc[2*j+1][0]), gelu_exact(acc[2*j+1][1]));
            u32 r3 = pkbf(gelu_exact(acc[2*j+1][2]), gelu_exact(acc[2*j+1][3]));
            *(uint4*)(s_h + ((mt * 24 + ktg) * 32 + lane) * 4) = make_uint4(r0, r1, r2, r3);
        }
    }
    __syncthreads();

    // ---- fc2: M=64, N half=64, K=384 ----
    float out[8][4];
    #pragma unroll
    for (int nt = 0; nt < 8; nt++) {
        float2 bv = *(const float2*)(b2 + e * C_ + (nh * 8 + nt) * 8 + tig * 2);
        out[nt][0] = bv.x; out[nt][1] = bv.y; out[nt][2] = bv.x; out[nt][3] = bv.y;
    }
    const u32* w2base = g_w2k + (e * 8 + nh * 4) * 3072 + lane * 4;
    #pragma unroll 2
    for (int kt = 0; kt < 24; kt++) {
        uint4 A = *(const uint4*)(s_h + ((mt * 24 + kt) * 32 + lane) * 4);
        #pragma unroll
        for (int j = 0; j < 4; j++) {
            uint4 Bv = *(const uint4*)(w2base + j * 3072 + kt * 128);
            mma_bf16(out[2*j][0],   out[2*j][1],   out[2*j][2],   out[2*j][3],
                     A.x, A.y, A.z, A.w, Bv.x, Bv.y);
            mma_bf16(out[2*j+1][0], out[2*j+1][1], out[2*j+1][2], out[2*j+1][3],
                     A.x, A.y, A.z, A.w, Bv.z, Bv.w);
        }
    }
    // ---- epilogue: gate * out -> slot buffer ----
    int m0 = mt * 16 + g, m1 = m0 + 8;
    float gg0 = s_g[m0], gg1 = s_g[m1];
    float* o0 = g_obuf + (size_t)(e * N_ + start + m0) * C_;
    float* o1 = g_obuf + (size_t)(e * N_ + start + m1) * C_;
    #pragma unroll
    for (int nt = 0; nt < 8; nt++) {
        int n0 = (nh * 8 + nt) * 8 + tig * 2;
        *(float2*)(o0 + n0) = make_float2(gg0 * out[nt][0], gg0 * out[nt][1]);
        *(float2*)(o1 + n0) = make_float2(gg1 * out[nt][2], gg1 * out[nt][3]);
    }
}

// ------------------- K5: combine slots + residual, NCHW -------------------
__global__ void __launch_bounds__(256) k_combine(const float* __restrict__ x,
                                                 float* __restrict__ dout) {
    __shared__ float s_y[C_ * 66];
    __shared__ int s_sl[128];
    int t = threadIdx.x;
    int n0 = blockIdx.x * 64;
    int b = n0 / HW_; int hw0 = n0 % HW_;
    if (t < 128) s_sl[t] = g_slot[n0 * 2 + t];
    __syncthreads();
    #pragma unroll
    for (int k = 0; k < 8; k++) {
        int lin = t + k * 256; int ts = lin >> 5, c4 = lin & 31;
        int s0 = s_sl[ts * 2], s1 = s_sl[ts * 2 + 1];
        float4 a = *(const float4*)(g_obuf + (size_t)s0 * C_ + c4 * 4);
        float4 bb = *(const float4*)(g_obuf + (size_t)s1 * C_ + c4 * 4);
        s_y[(c4 * 4 + 0) * 66 + ts] = a.x + bb.x;
        s_y[(c4 * 4 + 1) * 66 + ts] = a.y + bb.y;
        s_y[(c4 * 4 + 2) * 66 + ts] = a.z + bb.z;
        s_y[(c4 * 4 + 3) * 66 + ts] = a.w + bb.w;
    }
    __syncthreads();
    size_t base = (size_t)b * C_ * HW_ + hw0;
    for (int k = 0; k < 32; k++) {
        int lin = t + k * 256; int c = lin >> 6, tk = lin & 63;
        size_t idx = base + (size_t)c * HW_ + tk;
        dout[idx] = s_y[c * 66 + tk] + x[idx];
    }
}

// ------------------------------- K6: aux loss -------------------------------
__global__ void k_loss(float* __restrict__ dout, int has_loss) {
    __shared__ float s_imp[E_];
    int t = threadIdx.x;
    int e = t >> 5, lane = t & 31;
    if (t < 128) {
        int cnt = g_cnt[e];
        float s = 0.f;
        for (int i = lane; i < cnt; i += 32) s += g_gate[e * N_ + i];
        #pragma unroll
        for (int o = 16; o > 0; o >>= 1) s += __shfl_xor_sync(0xffffffff, s, o);
        if (lane == 0) s_imp[e] = s;
    }
    __syncthreads();
    if (t == 0 && has_loss) {
        float L[E_], I[E_];
        float mi = 0.f, ml = 0.f;
        for (int k = 0; k < E_; k++) {
            I[k] = s_imp[k]; L[k] = (float)g_cnt[k];
            mi += I[k]; ml += L[k];
        }
        mi *= 0.25f; ml *= 0.25f;
        float vi = 0.f, vl = 0.f;
        for (int k = 0; k < E_; k++) {
            float di = I[k] - mi, dl = L[k] - ml;
            vi += di * di; vl += dl * dl;
        }
        vi *= 0.25f; vl *= 0.25f;
        float loss = 1e-2f * (vi / (mi * mi + 1e-10f) + vl / (ml * ml + 1e-10f));
        dout[NCHW_] = loss;
    }
}

// --------------------------------- launcher ---------------------------------
extern "C" void kernel_launch(void* const* d_in, const int* in_sizes, int n_in,
                              void* d_out, int out_size) {
    const float* x      = (const float*)d_in[0];
    const float* prompt = (const float*)d_in[1];
    const float* w_lin  = (const float*)d_in[2];
    const float* b_lin  = (const float*)d_in[3];
    const float* w_conv = (const float*)d_in[4];
    const float* w_gate = (const float*)d_in[5];
    const float* w1     = (const float*)d_in[6];
    const float* b1     = (const float*)d_in[7];
    const float* w2     = (const float*)d_in[8];
    const float* b2     = (const float*)d_in[9];
    float* out = (float*)d_out;

    cudaFuncSetAttribute(k_expert, cudaFuncAttributeMaxDynamicSharedMemorySize, SMX_BYTES);

    k_mean<<<B_ * C_, 256>>>(x);
    k_prep<<<1, 256>>>(prompt, w_lin, b_lin, w_conv);
    k_pack<<<(196608 + E_ * HIDP_ + 255) / 256, 256>>>(w1, b1, w2);
    k_conv_gate<<<N_ / 64, 256>>>(x, w_gate);
    dim3 ge(N_ / 64, E_);
    k_expert<<<ge, 256, SMX_BYTES>>>(b2);
    k_combine<<<N_ / 64, 256>>>(x, out);
    k_loss<<<1, 128>>>(out, (out_size > NCHW_) ? 1 : 0);
}

// round 9
// speedup vs baseline: 3.6065x; 1.1428x over previous
#include <cuda_runtime.h>
#include <cuda_bf16.h>
#include <math.h>

#define B_     2
#define C_     128
#define HW_    36864
#define N_     73728
#define E_     4
#define HID_   340
#define HIDP_  384
#define NCHW_  9437184

typedef unsigned long long u64;
typedef unsigned int u32;

__device__ __forceinline__ float gelu_exact(float v) {
    return 0.5f * v * (1.0f + erff(v * 0.70710678118654752440f));
}
// pack {lo, hi} floats -> bf16x2 in one u32 (lo in low 16 bits)
__device__ __forceinline__ u32 pkbf(float lo, float hi) {
    u32 d; asm("cvt.rn.bf16x2.f32 %0, %1, %2;" : "=r"(d) : "f"(hi), "f"(lo)); return d;
}
__device__ __forceinline__ float2 upbf(u32 v) {
    __nv_bfloat162 b = *(__nv_bfloat162*)&v;
    return __bfloat1622float2(b);
}
__device__ __forceinline__ void mma_bf16(float& c0, float& c1, float& c2, float& c3,
                                         u32 a0, u32 a1, u32 a2, u32 a3, u32 b0, u32 b1) {
    asm("mma.sync.aligned.m16n8k16.row.col.f32.bf16.bf16.f32 "
        "{%0,%1,%2,%3}, {%4,%5,%6,%7}, {%8,%9}, {%0,%1,%2,%3};"
        : "+f"(c0), "+f"(c1), "+f"(c2), "+f"(c3)
        : "r"(a0), "r"(a1), "r"(a2), "r"(a3), "r"(b0), "r"(b1));
}

// ----------------------------- device scratch -----------------------------
__device__ float g_emb[B_ * C_];
__device__ float g_WbT[B_ * C_ * C_];          // [b][c][o]
__device__ u32   g_tyb[(size_t)N_ * 64];       // conv-out tokens, bf16x2 [n][cpair]
__device__ int   g_cnt[E_];
__device__ int   g_tok[E_ * N_];
__device__ float g_gate[E_ * N_];
__device__ int   g_slot[N_ * 2];
__device__ u32   g_obufh[(size_t)E_ * N_ * 64]; // gated expert outputs, bf16x2
// packed bf16 weights in m16n8k16 B-fragment order
__device__ u32   g_w1k[98304];                 // [e][24 pr][8 kt][32 lane][4]
__device__ u32   g_w2k[98304];                 // [e][8 pr][24 kt][32 lane][4]
__device__ u32   g_wck[16384];                 // conv: [b][8 pr][8 kt][32 lane][4]
__device__ float g_b1p[E_ * HIDP_];            // padded b1

// ----------------------------- K1: channel means -----------------------------
__global__ void k_mean(const float* __restrict__ x) {
    int row = blockIdx.x;                   // b*C + c
    int t = threadIdx.x;
    const float4* xr = (const float4*)(x + (size_t)row * HW_);
    float s = 0.f;
    for (int i = t; i < HW_ / 4; i += 256) {
        float4 v = xr[i];
        s += (v.x + v.y) + (v.z + v.w);
    }
    __shared__ float sm[256];
    sm[t] = s; __syncthreads();
    for (int o = 128; o > 0; o >>= 1) {
        if (t < o) sm[t] += sm[t + o];
        __syncthreads();
    }
    if (t == 0) g_emb[row] = sm[0] * (1.0f / (float)HW_);
}

// --------------------- K2: prompt softmax + fold conv W ---------------------
__global__ void k_prep(const float* __restrict__ prompt, const float* __restrict__ w_lin,
                       const float* __restrict__ b_lin, const float* __restrict__ w_conv) {
    int t = threadIdx.x;
    __shared__ float s_l[B_ * 5], s_pw[B_ * 5], s_sp[B_ * C_];
    if (t < E_) g_cnt[t] = 0;               // reset routing counters every launch
    if (t < B_ * 5) {
        int b = t / 5, p = t % 5;
        float a = b_lin[p];
        for (int c = 0; c < C_; c++) a += g_emb[b * C_ + c] * w_lin[p * C_ + c];
        s_l[t] = a;
    }
    __syncthreads();
    if (t < B_) {
        float m = s_l[t * 5];
        for (int p = 1; p < 5; p++) m = fmaxf(m, s_l[t * 5 + p]);
        float e[5]; float den = 0.f;
        for (int p = 0; p < 5; p++) { e[p] = expf(s_l[t * 5 + p] - m); den += e[p]; }
        for (int p = 0; p < 5; p++) s_pw[t * 5 + p] = e[p] / den;
    }
    __syncthreads();
    {
        int b = t >> 7, c = t & 127;
        float a = 0.f;
        for (int p = 0; p < 5; p++) a += s_pw[b * 5 + p] * prompt[p * C_ + c];
        s_sp[t] = a;
    }
    __syncthreads();
    for (int i = t; i < B_ * C_ * C_; i += 256) {
        int b = i >> 14; int rem = i & 16383; int c = rem >> 7; int o = rem & 127;
        g_WbT[i] = w_conv[o * C_ + c] * s_sp[b * C_ + c];
    }
}

// ----------------- K2b: pack weights to bf16 fragments -----------------
__global__ void k_pack(const float* __restrict__ w1, const float* __restrict__ b1,
                       const float* __restrict__ w2) {
    int i = blockIdx.x * 256 + threadIdx.x;
    if (i < 98304) {                 // w1k: n8 pairs over HIDP, k over C
        int r = i & 3, lane = (i >> 2) & 31, kt = (i >> 7) & 7;
        int pe = i >> 10; int pr = pe % 24; int e = pe / 24;
        int n = (pr * 2 + (r >> 1)) * 8 + (lane >> 2);
        int k = kt * 16 + (lane & 3) * 2 + (r & 1) * 8;
        float v0 = 0.f, v1 = 0.f;
        if (n < HID_) {
            v0 = w1[((size_t)(e * C_ + k)) * HID_ + n];
            v1 = w1[((size_t)(e * C_ + k + 1)) * HID_ + n];
        }
        g_w1k[i] = pkbf(v0, v1);
    } else if (i < 196608) {         // w2k: n8 pairs over C, k over HIDP
        int j = i - 98304;
        int r = j & 3, lane = (j >> 2) & 31;
        int rest = j >> 7; int kt = rest % 24; int pe = rest / 24;
        int pr = pe & 7; int e = pe >> 3;
        int n = (pr * 2 + (r >> 1)) * 8 + (lane >> 2);
        int k = kt * 16 + (lane & 3) * 2 + (r & 1) * 8;
        float v0 = (k < HID_)     ? w2[((size_t)(e * HID_ + k)) * C_ + n]     : 0.f;
        float v1 = (k + 1 < HID_) ? w2[((size_t)(e * HID_ + k + 1)) * C_ + n] : 0.f;
        g_w2k[j] = pkbf(v0, v1);
    } else if (i < 196608 + E_ * HIDP_) {
        int l = i - 196608; int e = l / HIDP_, n = l % HIDP_;
        g_b1p[l] = (n < HID_) ? b1[e * HID_ + n] : 0.f;
    } else if (i < 196608 + E_ * HIDP_ + 16384) {   // conv weights (needs g_WbT)
        int j = i - (196608 + E_ * HIDP_);
        int r = j & 3, lane = (j >> 2) & 31, kt = (j >> 7) & 7;
        int pe = j >> 10; int pr = pe & 7; int b = pe >> 3;
        int n = (pr * 2 + (r >> 1)) * 8 + (lane >> 2);
        int k = kt * 16 + (lane & 3) * 2 + (r & 1) * 8;
        float v0 = g_WbT[b * 16384 + k * 128 + n];
        float v1 = g_WbT[b * 16384 + (k + 1) * 128 + n];
        g_wck[j] = pkbf(v0, v1);
    }
}

// ---------------- K3: 1x1 conv (bf16 HMMA) + gating + top-2 scatter ----------------
// dyn smem (u32 words): s_x[128*66 f] | s_a[4096] | s_lg[256 f]
#define CV_SA  8448
#define CV_LG  12544
#define CV_TOT 12800
#define CV_BYTES (CV_TOT * 4)

__global__ void __launch_bounds__(256, 2) k_conv_gate(const float* __restrict__ x,
                                                      const float* __restrict__ w_gate) {
    extern __shared__ __align__(16) u32 cvsm[];
    float* s_x  = (float*)cvsm;
    u32*   s_a  = cvsm + CV_SA;
    float* s_lg = (float*)(cvsm + CV_LG);
    int t = threadIdx.x;
    int n0 = blockIdx.x * 64;
    int b = n0 / HW_; int hw0 = n0 % HW_;
    const float* xb = x + (size_t)b * C_ * HW_ + hw0;
    for (int i = t; i < C_ * 64; i += 256) {
        int c = i >> 6, tk = i & 63;
        s_x[c * 66 + tk] = xb[(size_t)c * HW_ + tk];
    }
    __syncthreads();
    {   // gating logits (fp32, exact): thread = (expert, token)
        int e = t >> 6, tk = t & 63;
        float a = 0.f;
        #pragma unroll 8
        for (int c = 0; c < C_; c++) a += s_x[c * 66 + tk] * w_gate[c * 4 + e];
        s_lg[tk * 4 + e] = a;
    }
    // build bf16 A-fragments from s_x
    #pragma unroll
    for (int i = 0; i < 16; i++) {
        int idx = t + i * 256;           // 64 tokens x 64 col-pairs
        int m = idx >> 6, cp = idx & 63, c = cp * 2;
        float v0 = s_x[c * 66 + m], v1 = s_x[(c + 1) * 66 + m];
        int mt = m >> 4, mr = m & 15, gg = mr & 7, hi = mr >> 3;
        int kt = c >> 4, ko = c & 15, half = ko >> 3, tg = (ko & 7) >> 1;
        int lane = gg * 4 + tg, reg = half * 2 + hi;
        s_a[((mt * 8 + kt) * 32 + lane) * 4 + reg] = pkbf(v0, v1);
    }
    __syncthreads();
    if (t < 64) {       // top-2 + softmax + scatter
        float l[4];
        #pragma unroll
        for (int e = 0; e < 4; e++) l[e] = s_lg[t * 4 + e];
        int e0 = 0; float m0 = l[0];
        #pragma unroll
        for (int e = 1; e < 4; e++) if (l[e] > m0) { m0 = l[e]; e0 = e; }
        int e1 = (e0 == 0) ? 1 : 0; float m1 = l[e1];
        #pragma unroll
        for (int e = 0; e < 4; e++) if (e != e0 && l[e] > m1) { m1 = l[e]; e1 = e; }
        float ex = expf(m1 - m0);
        float g0 = 1.0f / (1.0f + ex);
        float g1 = ex * g0;
        int n = n0 + t;
        int p0 = atomicAdd(&g_cnt[e0], 1);
        g_tok[e0 * N_ + p0] = n; g_gate[e0 * N_ + p0] = g0;
        g_slot[n * 2 + 0] = e0 * N_ + p0;
        int p1 = atomicAdd(&g_cnt[e1], 1);
        g_tok[e1 * N_ + p1] = n; g_gate[e1 * N_ + p1] = g1;
        g_slot[n * 2 + 1] = e1 * N_ + p1;
    }
    // conv HMMA: M=64 (mt), N=128 (nh half = 64 cols = 4 pr), K=128 (8 kt)
    int warp = t >> 5, lane = t & 31, gg = lane >> 2, tg = lane & 3;
    int mt = warp & 3, nh = warp >> 2;
    float acc[8][4];
    #pragma unroll
    for (int nt = 0; nt < 8; nt++)
        #pragma unroll
        for (int r = 0; r < 4; r++) acc[nt][r] = 0.f;
    const u32* wbase = g_wck + (b * 8 + nh * 4) * 1024 + lane * 4;
    #pragma unroll
    for (int kt = 0; kt < 8; kt++) {
        uint4 A = *(const uint4*)(s_a + ((mt * 8 + kt) * 32 + lane) * 4);
        #pragma unroll
        for (int j = 0; j < 4; j++) {
            uint4 Bv = *(const uint4*)(wbase + j * 1024 + kt * 128);
            mma_bf16(acc[2*j][0],   acc[2*j][1],   acc[2*j][2],   acc[2*j][3],
                     A.x, A.y, A.z, A.w, Bv.x, Bv.y);
            mma_bf16(acc[2*j+1][0], acc[2*j+1][1], acc[2*j+1][2], acc[2*j+1][3],
                     A.x, A.y, A.z, A.w, Bv.z, Bv.w);
        }
    }
    // store ty directly as bf16x2 col-pairs
    int m0 = mt * 16 + gg, m1 = m0 + 8;
    u32* o0 = g_tyb + (size_t)(n0 + m0) * 64;
    u32* o1 = g_tyb + (size_t)(n0 + m1) * 64;
    #pragma unroll
    for (int nt = 0; nt < 8; nt++) {
        int cp = (nh * 8 + nt) * 4 + tg;
        o0[cp] = pkbf(acc[nt][0], acc[nt][1]);
        o1[cp] = pkbf(acc[nt][2], acc[nt][3]);
    }
}

// ---------------- K4: fused expert fc1 + gelu + fc2 (bf16 HMMA) ----------------
#define SMU_A   0
#define SMU_H   4096
#define SMU_G   16384
#define SMU_TK  16448
#define SMU_TOT 16512
#define SMX_BYTES (SMU_TOT * 4)

__global__ void __launch_bounds__(256, 2) k_expert(const float* __restrict__ b2) {
    extern __shared__ __align__(16) u32 smu[];
    u32*   s_a  = smu + SMU_A;
    u32*   s_h  = smu + SMU_H;
    float* s_g  = (float*)(smu + SMU_G);
    int*   s_tk = (int*)(smu + SMU_TK);

    int e = blockIdx.y;
    int cnt = g_cnt[e];
    int start = blockIdx.x * 64;
    if (start >= cnt) return;
    int t = threadIdx.x;
    if (t < 64) {
        int idx = start + t;
        if (idx < cnt) { s_tk[t] = g_tok[e * N_ + idx]; s_g[t] = g_gate[e * N_ + idx]; }
        else           { s_tk[t] = 0;                   s_g[t] = 0.f; }
    }
    __syncthreads();
    // gather pre-packed bf16x2 ty -> A-fragments in smem
    #pragma unroll
    for (int i = 0; i < 16; i++) {
        int idx = t + i * 256;              // 64 tokens x 64 col-pairs
        int m = idx >> 6, cp = idx & 63, c = cp * 2;
        int tok = s_tk[m];
        u32 v = g_tyb[(size_t)tok * 64 + cp];
        int mt = m >> 4, mr = m & 15, gg = mr & 7, hi = mr >> 3;
        int kt = c >> 4, ko = c & 15, half = ko >> 3, tg = (ko & 7) >> 1;
        int lane = gg * 4 + tg, reg = half * 2 + hi;
        s_a[((mt * 8 + kt) * 32 + lane) * 4 + reg] = v;
    }
    __syncthreads();

    int warp = t >> 5, lane = t & 31, gg = lane >> 2, tg = lane & 3;
    int mt = warp & 3, nh = warp >> 2;

    // ---- fc1: two passes of 12 n8-tiles; output to s_h as fc2 A-fragments ----
    for (int p = 0; p < 2; p++) {
        float acc[12][4];
        #pragma unroll
        for (int j2 = 0; j2 < 12; j2++) {
            int nt = nh * 24 + p * 12 + j2;
            float2 bv = *(const float2*)(g_b1p + e * HIDP_ + nt * 8 + tg * 2);
            acc[j2][0] = bv.x; acc[j2][1] = bv.y; acc[j2][2] = bv.x; acc[j2][3] = bv.y;
        }
        const u32* wbase = g_w1k + (e * 24 + nh * 12 + p * 6) * 1024 + lane * 4;
        #pragma unroll
        for (int kt = 0; kt < 8; kt++) {
            uint4 A = *(const uint4*)(s_a + ((mt * 8 + kt) * 32 + lane) * 4);
            #pragma unroll
            for (int j = 0; j < 6; j++) {
                uint4 Bv = *(const uint4*)(wbase + j * 1024 + kt * 128);
                mma_bf16(acc[2*j][0],   acc[2*j][1],   acc[2*j][2],   acc[2*j][3],
                         A.x, A.y, A.z, A.w, Bv.x, Bv.y);
                mma_bf16(acc[2*j+1][0], acc[2*j+1][1], acc[2*j+1][2], acc[2*j+1][3],
                         A.x, A.y, A.z, A.w, Bv.z, Bv.w);
            }
        }
        #pragma unroll
        for (int j = 0; j < 6; j++) {       // gelu + pack: accum frag pair == fc2 A frag
            int ktg = nh * 12 + p * 6 + j;
            u32 r0 = pkbf(gelu_exact(acc[2*j][0]),   gelu_exact(acc[2*j][1]));
            u32 r1 = pkbf(gelu_exact(acc[2*j][2]),   gelu_exact(acc[2*j][3]));
            u32 r2 = pkbf(gelu_exact(acc[2*j+1][0]), gelu_exact(acc[2*j+1][1]));
            u32 r3 = pkbf(gelu_exact(acc[2*j+1][2]), gelu_exact(acc[2*j+1][3]));
            *(uint4*)(s_h + ((mt * 24 + ktg) * 32 + lane) * 4) = make_uint4(r0, r1, r2, r3);
        }
    }
    __syncthreads();

    // ---- fc2: M=64, N half=64, K=384 ----
    float out[8][4];
    #pragma unroll
    for (int nt = 0; nt < 8; nt++) {
        float2 bv = *(const float2*)(b2 + e * C_ + (nh * 8 + nt) * 8 + tg * 2);
        out[nt][0] = bv.x; out[nt][1] = bv.y; out[nt][2] = bv.x; out[nt][3] = bv.y;
    }
    const u32* w2base = g_w2k + (e * 8 + nh * 4) * 3072 + lane * 4;
    #pragma unroll 2
    for (int kt = 0; kt < 24; kt++) {
        uint4 A = *(const uint4*)(s_h + ((mt * 24 + kt) * 32 + lane) * 4);
        #pragma unroll
        for (int j = 0; j < 4; j++) {
            uint4 Bv = *(const uint4*)(w2base + j * 3072 + kt * 128);
            mma_bf16(out[2*j][0],   out[2*j][1],   out[2*j][2],   out[2*j][3],
                     A.x, A.y, A.z, A.w, Bv.x, Bv.y);
            mma_bf16(out[2*j+1][0], out[2*j+1][1], out[2*j+1][2], out[2*j+1][3],
                     A.x, A.y, A.z, A.w, Bv.z, Bv.w);
        }
    }
    // ---- epilogue: gate * out -> bf16x2 slot buffer ----
    int m0 = mt * 16 + gg, m1 = m0 + 8;
    float gg0 = s_g[m0], gg1 = s_g[m1];
    u32* o0 = g_obufh + (size_t)(e * N_ + start + m0) * 64;
    u32* o1 = g_obufh + (size_t)(e * N_ + start + m1) * 64;
    #pragma unroll
    for (int nt = 0; nt < 8; nt++) {
        int cp = (nh * 8 + nt) * 4 + tg;
        o0[cp] = pkbf(gg0 * out[nt][0], gg0 * out[nt][1]);
        o1[cp] = pkbf(gg1 * out[nt][2], gg1 * out[nt][3]);
    }
}

// ------------------- K5: combine slots + residual, NCHW -------------------
__global__ void __launch_bounds__(256) k_combine(const float* __restrict__ x,
                                                 float* __restrict__ dout) {
    __shared__ float s_y[C_ * 66];
    __shared__ int s_sl[128];
    int t = threadIdx.x;
    int n0 = blockIdx.x * 64;
    int b = n0 / HW_; int hw0 = n0 % HW_;
    if (t < 128) s_sl[t] = g_slot[n0 * 2 + t];
    __syncthreads();
    #pragma unroll
    for (int i = 0; i < 16; i++) {
        int idx = t + i * 256; int ts = idx >> 6, cp = idx & 63, c = cp * 2;
        int s0 = s_sl[ts * 2], s1 = s_sl[ts * 2 + 1];
        float2 a = upbf(g_obufh[(size_t)s0 * 64 + cp]);
        float2 bb = upbf(g_obufh[(size_t)s1 * 64 + cp]);
        s_y[c * 66 + ts]       = a.x + bb.x;
        s_y[(c + 1) * 66 + ts] = a.y + bb.y;
    }
    __syncthreads();
    size_t base = (size_t)b * C_ * HW_ + hw0;
    for (int k = 0; k < 32; k++) {
        int lin = t + k * 256; int c = lin >> 6, tk = lin & 63;
        size_t idx = base + (size_t)c * HW_ + tk;
        dout[idx] = s_y[c * 66 + tk] + x[idx];
    }
}

// ------------------------------- K6: aux loss -------------------------------
__global__ void k_loss(float* __restrict__ dout, int has_loss) {
    __shared__ float s_imp[E_];
    int t = threadIdx.x;
    int e = t >> 5, lane = t & 31;
    if (t < 128) {
        int cnt = g_cnt[e];
        float s = 0.f;
        for (int i = lane; i < cnt; i += 32) s += g_gate[e * N_ + i];
        #pragma unroll
        for (int o = 16; o > 0; o >>= 1) s += __shfl_xor_sync(0xffffffff, s, o);
        if (lane == 0) s_imp[e] = s;
    }
    __syncthreads();
    if (t == 0 && has_loss) {
        float L[E_], I[E_];
        float mi = 0.f, ml = 0.f;
        for (int k = 0; k < E_; k++) {
            I[k] = s_imp[k]; L[k] = (float)g_cnt[k];
            mi += I[k]; ml += L[k];
        }
        mi *= 0.25f; ml *= 0.25f;
        float vi = 0.f, vl = 0.f;
        for (int k = 0; k < E_; k++) {
            float di = I[k] - mi, dl = L[k] - ml;
            vi += di * di; vl += dl * dl;
        }
        vi *= 0.25f; vl *= 0.25f;
        float loss = 1e-2f * (vi / (mi * mi + 1e-10f) + vl / (ml * ml + 1e-10f));
        dout[NCHW_] = loss;
    }
}

// --------------------------------- launcher ---------------------------------
extern "C" void kernel_launch(void* const* d_in, const int* in_sizes, int n_in,
                              void* d_out, int out_size) {
    const float* x      = (const float*)d_in[0];
    const float* prompt = (const float*)d_in[1];
    const float* w_lin  = (const float*)d_in[2];
    const float* b_lin  = (const float*)d_in[3];
    const float* w_conv = (const float*)d_in[4];
    const float* w_gate = (const float*)d_in[5];
    const float* w1     = (const float*)d_in[6];
    const float* b1     = (const float*)d_in[7];
    const float* w2     = (const float*)d_in[8];
    const float* b2     = (const float*)d_in[9];
    float* out = (float*)d_out;

    cudaFuncSetAttribute(k_expert, cudaFuncAttributeMaxDynamicSharedMemorySize, SMX_BYTES);
    cudaFuncSetAttribute(k_conv_gate, cudaFuncAttributeMaxDynamicSharedMemorySize, CV_BYTES);

    k_mean<<<B_ * C_, 256>>>(x);
    k_prep<<<1, 256>>>(prompt, w_lin, b_lin, w_conv);
    int packn = 196608 + E_ * HIDP_ + 16384;
    k_pack<<<(packn + 255) / 256, 256>>>(w1, b1, w2);
    k_conv_gate<<<N_ / 64, 256, CV_BYTES>>>(x, w_gate);
    dim3 ge(N_ / 64, E_);
    k_expert<<<ge, 256, SMX_BYTES>>>(b2);
    k_combine<<<N_ / 64, 256>>>(x, out);
    k_loss<<<1, 128>>>(out, (out_size > NCHW_) ? 1 : 0);
}

// round 10
// speedup vs baseline: 3.7346x; 1.0355x over previous
#include <cuda_runtime.h>
#include <cuda_bf16.h>
#include <math.h>

#define B_     2
#define C_     128
#define HW_    36864
#define N_     73728
#define E_     4
#define HID_   340
#define HIDP_  384
#define NCHW_  9437184

typedef unsigned long long u64;
typedef unsigned int u32;

__device__ __forceinline__ float gelu_exact(float v) {
    return 0.5f * v * (1.0f + erff(v * 0.70710678118654752440f));
}
// pack {lo, hi} floats -> bf16x2 in one u32 (lo in low 16 bits)
__device__ __forceinline__ u32 pkbf(float lo, float hi) {
    u32 d; asm("cvt.rn.bf16x2.f32 %0, %1, %2;" : "=r"(d) : "f"(hi), "f"(lo)); return d;
}
__device__ __forceinline__ float2 upbf(u32 v) {
    __nv_bfloat162 b = *(__nv_bfloat162*)&v;
    return __bfloat1622float2(b);
}
__device__ __forceinline__ void mma_bf16(float& c0, float& c1, float& c2, float& c3,
                                         u32 a0, u32 a1, u32 a2, u32 a3, u32 b0, u32 b1) {
    asm("mma.sync.aligned.m16n8k16.row.col.f32.bf16.bf16.f32 "
        "{%0,%1,%2,%3}, {%4,%5,%6,%7}, {%8,%9}, {%0,%1,%2,%3};"
        : "+f"(c0), "+f"(c1), "+f"(c2), "+f"(c3)
        : "r"(a0), "r"(a1), "r"(a2), "r"(a3), "r"(b0), "r"(b1));
}

// ----------------------------- device scratch -----------------------------
__device__ float g_part[1024];                 // partial row sums (mean stage 1)
__device__ float g_emb[B_ * C_];
__device__ float g_WbT[B_ * C_ * C_];          // [b][c][o]
__device__ u32   g_tyb[(size_t)N_ * 64];       // conv-out tokens, bf16x2 [n][cpair]
__device__ int   g_cnt[E_];
__device__ int   g_tok[E_ * N_];
__device__ float g_gate[E_ * N_];
__device__ int   g_slot[N_ * 2];
__device__ u32   g_obufh[(size_t)E_ * N_ * 64]; // gated expert outputs, bf16x2
// packed bf16 weights in m16n8k16 B-fragment order
__device__ u32   g_w1k[98304];                 // [e][24 pr][8 kt][32 lane][4]
__device__ u32   g_w2k[98304];                 // [e][8 pr][24 kt][32 lane][4]
__device__ u32   g_wck[16384];                 // conv: [b][8 pr][8 kt][32 lane][4]
__device__ float g_b1p[E_ * HIDP_];            // padded b1

// ---------------------- K1: channel means (stage 1) ----------------------
__global__ void k_mean1(const float* __restrict__ x) {
    int part = blockIdx.x;                  // row*4 + q
    int row = part >> 2, q = part & 3;
    int t = threadIdx.x;
    const float4* xr = (const float4*)(x + (size_t)row * HW_) + q * 2304;
    float s = 0.f;
    #pragma unroll
    for (int i = 0; i < 9; i++) {
        float4 v = xr[t + i * 256];
        s += (v.x + v.y) + (v.z + v.w);
    }
    __shared__ float sm[256];
    sm[t] = s; __syncthreads();
    for (int o = 128; o > 0; o >>= 1) {
        if (t < o) sm[t] += sm[t + o];
        __syncthreads();
    }
    if (t == 0) g_part[part] = sm[0];
}

// ------ K2: mean reduce + prompt softmax + fold conv W (256 threads) ------
__global__ void k_prep(const float* __restrict__ prompt, const float* __restrict__ w_lin,
                       const float* __restrict__ b_lin, const float* __restrict__ w_conv) {
    int t = threadIdx.x;
    __shared__ float s_l[B_ * 5], s_pw[B_ * 5], s_sp[B_ * C_];
    {   // finish channel means
        float4 p = *(const float4*)(g_part + t * 4);
        g_emb[t] = ((p.x + p.y) + (p.z + p.w)) * (1.0f / (float)HW_);
    }
    if (t < E_) g_cnt[t] = 0;               // reset routing counters every launch
    __syncthreads();
    if (t < B_ * 5) {
        int b = t / 5, p = t % 5;
        float a = b_lin[p];
        for (int c = 0; c < C_; c++) a += g_emb[b * C_ + c] * w_lin[p * C_ + c];
        s_l[t] = a;
    }
    __syncthreads();
    if (t < B_) {
        float m = s_l[t * 5];
        for (int p = 1; p < 5; p++) m = fmaxf(m, s_l[t * 5 + p]);
        float e[5]; float den = 0.f;
        for (int p = 0; p < 5; p++) { e[p] = expf(s_l[t * 5 + p] - m); den += e[p]; }
        for (int p = 0; p < 5; p++) s_pw[t * 5 + p] = e[p] / den;
    }
    __syncthreads();
    {
        int b = t >> 7, c = t & 127;
        float a = 0.f;
        for (int p = 0; p < 5; p++) a += s_pw[b * 5 + p] * prompt[p * C_ + c];
        s_sp[t] = a;
    }
    __syncthreads();
    for (int i = t; i < B_ * C_ * C_; i += 256) {
        int b = i >> 14; int rem = i & 16383; int c = rem >> 7; int o = rem & 127;
        g_WbT[i] = w_conv[o * C_ + c] * s_sp[b * C_ + c];
    }
}

// ----------------- K2b: pack weights to bf16 fragments -----------------
__global__ void k_pack(const float* __restrict__ w1, const float* __restrict__ b1,
                       const float* __restrict__ w2) {
    int i = blockIdx.x * 256 + threadIdx.x;
    if (i < 98304) {                 // w1k: n8 pairs over HIDP, k over C
        int r = i & 3, lane = (i >> 2) & 31, kt = (i >> 7) & 7;
        int pe = i >> 10; int pr = pe % 24; int e = pe / 24;
        int n = (pr * 2 + (r >> 1)) * 8 + (lane >> 2);
        int k = kt * 16 + (lane & 3) * 2 + (r & 1) * 8;
        float v0 = 0.f, v1 = 0.f;
        if (n < HID_) {
            v0 = w1[((size_t)(e * C_ + k)) * HID_ + n];
            v1 = w1[((size_t)(e * C_ + k + 1)) * HID_ + n];
        }
        g_w1k[i] = pkbf(v0, v1);
    } else if (i < 196608) {         // w2k: n8 pairs over C, k over HIDP
        int j = i - 98304;
        int r = j & 3, lane = (j >> 2) & 31;
        int rest = j >> 7; int kt = rest % 24; int pe = rest / 24;
        int pr = pe & 7; int e = pe >> 3;
        int n = (pr * 2 + (r >> 1)) * 8 + (lane >> 2);
        int k = kt * 16 + (lane & 3) * 2 + (r & 1) * 8;
        float v0 = (k < HID_)     ? w2[((size_t)(e * HID_ + k)) * C_ + n]     : 0.f;
        float v1 = (k + 1 < HID_) ? w2[((size_t)(e * HID_ + k + 1)) * C_ + n] : 0.f;
        g_w2k[j] = pkbf(v0, v1);
    } else if (i < 196608 + E_ * HIDP_) {
        int l = i - 196608; int e = l / HIDP_, n = l % HIDP_;
        g_b1p[l] = (n < HID_) ? b1[e * HID_ + n] : 0.f;
    } else if (i < 196608 + E_ * HIDP_ + 16384) {   // conv weights (needs g_WbT)
        int j = i - (196608 + E_ * HIDP_);
        int r = j & 3, lane = (j >> 2) & 31, kt = (j >> 7) & 7;
        int pe = j >> 10; int pr = pe & 7; int b = pe >> 3;
        int n = (pr * 2 + (r >> 1)) * 8 + (lane >> 2);
        int k = kt * 16 + (lane & 3) * 2 + (r & 1) * 8;
        float v0 = g_WbT[b * 16384 + k * 128 + n];
        float v1 = g_WbT[b * 16384 + (k + 1) * 128 + n];
        g_wck[j] = pkbf(v0, v1);
    }
}

// ---------------- K3: 1x1 conv (bf16 HMMA) + gating + top-2 scatter ----------------
// smem words: s_x[64*130 f] | s_wg[512 f] | s_lg[256 f] | s_a[4096 u32]
#define CVP    130
#define CV_WG  8320
#define CV_LG  8832
#define CV_SA  9088
#define CV_TOT 13184
#define CV_BYTES (CV_TOT * 4)

__global__ void __launch_bounds__(256, 2) k_conv_gate(const float* __restrict__ x,
                                                      const float* __restrict__ w_gate) {
    extern __shared__ __align__(16) u32 cvsm[];
    float* s_x  = (float*)cvsm;                 // [tok][CVP]
    float* s_wg = (float*)(cvsm + CV_WG);
    float* s_lg = (float*)(cvsm + CV_LG);
    u32*   s_a  = cvsm + CV_SA;
    int t = threadIdx.x;
    int n0 = blockIdx.x * 64;
    int b = n0 / HW_; int hw0 = n0 % HW_;
    const float* xb = x + (size_t)b * C_ * HW_ + hw0;
    s_wg[t] = w_gate[t]; s_wg[t + 256] = w_gate[t + 256];
    #pragma unroll
    for (int i = 0; i < 32; i++) {
        int idx = t + i * 256; int c = idx >> 6, tk = idx & 63;
        s_x[tk * CVP + c] = xb[(size_t)c * HW_ + tk];
    }
    __syncthreads();
    {   // gating logits (fp32): thread = (expert, token), 4-way ILP
        int e = t >> 6, tk = t & 63;
        const float* xr = s_x + tk * CVP;
        float a0 = 0.f, a1 = 0.f, a2 = 0.f, a3 = 0.f;
        #pragma unroll
        for (int c = 0; c < C_; c += 4) {
            a0 = fmaf(xr[c],     s_wg[c * 4 + e],       a0);
            a1 = fmaf(xr[c + 1], s_wg[(c + 1) * 4 + e], a1);
            a2 = fmaf(xr[c + 2], s_wg[(c + 2) * 4 + e], a2);
            a3 = fmaf(xr[c + 3], s_wg[(c + 3) * 4 + e], a3);
        }
        s_lg[tk * 4 + e] = (a0 + a1) + (a2 + a3);
    }
    // build bf16 A-fragments (conflict-free float2 reads)
    #pragma unroll
    for (int i = 0; i < 16; i++) {
        int idx = t + i * 256;           // 64 tokens x 64 col-pairs
        int m = idx >> 6, cp = idx & 63, c = cp * 2;
        float2 v = *(const float2*)(s_x + m * CVP + c);
        int mt = m >> 4, mr = m & 15, gg = mr & 7, hi = mr >> 3;
        int kt = c >> 4, ko = c & 15, half = ko >> 3, tg = (ko & 7) >> 1;
        int lane = gg * 4 + tg, reg = half * 2 + hi;
        s_a[((mt * 8 + kt) * 32 + lane) * 4 + reg] = pkbf(v.x, v.y);
    }
    __syncthreads();
    if (t < 64) {       // top-2 + softmax + scatter
        float l[4];
        #pragma unroll
        for (int e = 0; e < 4; e++) l[e] = s_lg[t * 4 + e];
        int e0 = 0; float m0 = l[0];
        #pragma unroll
        for (int e = 1; e < 4; e++) if (l[e] > m0) { m0 = l[e]; e0 = e; }
        int e1 = (e0 == 0) ? 1 : 0; float m1 = l[e1];
        #pragma unroll
        for (int e = 0; e < 4; e++) if (e != e0 && l[e] > m1) { m1 = l[e]; e1 = e; }
        float ex = expf(m1 - m0);
        float g0 = 1.0f / (1.0f + ex);
        float g1 = ex * g0;
        int n = n0 + t;
        int p0 = atomicAdd(&g_cnt[e0], 1);
        g_tok[e0 * N_ + p0] = n; g_gate[e0 * N_ + p0] = g0;
        g_slot[n * 2 + 0] = e0 * N_ + p0;
        int p1 = atomicAdd(&g_cnt[e1], 1);
        g_tok[e1 * N_ + p1] = n; g_gate[e1 * N_ + p1] = g1;
        g_slot[n * 2 + 1] = e1 * N_ + p1;
    }
    // conv HMMA: M=64 (mt), N half=64 (nh), K=128 (8 kt)
    int warp = t >> 5, lane = t & 31, gg = lane >> 2, tg = lane & 3;
    int mt = warp & 3, nh = warp >> 2;
    float acc[8][4];
    #pragma unroll
    for (int nt = 0; nt < 8; nt++)
        #pragma unroll
        for (int r = 0; r < 4; r++) acc[nt][r] = 0.f;
    const u32* wbase = g_wck + (b * 8 + nh * 4) * 1024 + lane * 4;
    #pragma unroll
    for (int kt = 0; kt < 8; kt++) {
        uint4 A = *(const uint4*)(s_a + ((mt * 8 + kt) * 32 + lane) * 4);
        #pragma unroll
        for (int j = 0; j < 4; j++) {
            uint4 Bv = *(const uint4*)(wbase + j * 1024 + kt * 128);
            mma_bf16(acc[2*j][0],   acc[2*j][1],   acc[2*j][2],   acc[2*j][3],
                     A.x, A.y, A.z, A.w, Bv.x, Bv.y);
            mma_bf16(acc[2*j+1][0], acc[2*j+1][1], acc[2*j+1][2], acc[2*j+1][3],
                     A.x, A.y, A.z, A.w, Bv.z, Bv.w);
        }
    }
    // store ty directly as bf16x2 col-pairs
    int m0 = mt * 16 + gg, m1 = m0 + 8;
    u32* o0 = g_tyb + (size_t)(n0 + m0) * 64;
    u32* o1 = g_tyb + (size_t)(n0 + m1) * 64;
    #pragma unroll
    for (int nt = 0; nt < 8; nt++) {
        int cp = (nh * 8 + nt) * 4 + tg;
        o0[cp] = pkbf(acc[nt][0], acc[nt][1]);
        o1[cp] = pkbf(acc[nt][2], acc[nt][3]);
    }
}

// ---------------- K4: fused expert fc1 + gelu + fc2 (bf16 HMMA) ----------------
#define SMU_A   0
#define SMU_H   4096
#define SMU_G   16384
#define SMU_TK  16448
#define SMU_TOT 16512
#define SMX_BYTES (SMU_TOT * 4)

__global__ void __launch_bounds__(256, 2) k_expert(const float* __restrict__ b2) {
    extern __shared__ __align__(16) u32 smu[];
    u32*   s_a  = smu + SMU_A;
    u32*   s_h  = smu + SMU_H;
    float* s_g  = (float*)(smu + SMU_G);
    int*   s_tk = (int*)(smu + SMU_TK);

    int e = blockIdx.y;
    int cnt = g_cnt[e];
    int start = blockIdx.x * 64;
    if (start >= cnt) return;
    int t = threadIdx.x;
    if (t < 64) {
        int idx = start + t;
        if (idx < cnt) { s_tk[t] = g_tok[e * N_ + idx]; s_g[t] = g_gate[e * N_ + idx]; }
        else           { s_tk[t] = 0;                   s_g[t] = 0.f; }
    }
    __syncthreads();
    // gather pre-packed bf16x2 ty -> A-fragments in smem
    #pragma unroll
    for (int i = 0; i < 16; i++) {
        int idx = t + i * 256;              // 64 tokens x 64 col-pairs
        int m = idx >> 6, cp = idx & 63, c = cp * 2;
        int tok = s_tk[m];
        u32 v = g_tyb[(size_t)tok * 64 + cp];
        int mt = m >> 4, mr = m & 15, gg = mr & 7, hi = mr >> 3;
        int kt = c >> 4, ko = c & 15, half = ko >> 3, tg = (ko & 7) >> 1;
        int lane = gg * 4 + tg, reg = half * 2 + hi;
        s_a[((mt * 8 + kt) * 32 + lane) * 4 + reg] = v;
    }
    __syncthreads();

    int warp = t >> 5, lane = t & 31, gg = lane >> 2, tg = lane & 3;
    int mt = warp & 3, nh = warp >> 2;

    // ---- fc1: two passes of 12 n8-tiles; output to s_h as fc2 A-fragments ----
    for (int p = 0; p < 2; p++) {
        float acc[12][4];
        #pragma unroll
        for (int j2 = 0; j2 < 12; j2++) {
            int nt = nh * 24 + p * 12 + j2;
            float2 bv = *(const float2*)(g_b1p + e * HIDP_ + nt * 8 + tg * 2);
            acc[j2][0] = bv.x; acc[j2][1] = bv.y; acc[j2][2] = bv.x; acc[j2][3] = bv.y;
        }
        const u32* wbase = g_w1k + (e * 24 + nh * 12 + p * 6) * 1024 + lane * 4;
        #pragma unroll
        for (int kt = 0; kt < 8; kt++) {
            uint4 A = *(const uint4*)(s_a + ((mt * 8 + kt) * 32 + lane) * 4);
            #pragma unroll
            for (int j = 0; j < 6; j++) {
                uint4 Bv = *(const uint4*)(wbase + j * 1024 + kt * 128);
                mma_bf16(acc[2*j][0],   acc[2*j][1],   acc[2*j][2],   acc[2*j][3],
                         A.x, A.y, A.z, A.w, Bv.x, Bv.y);
                mma_bf16(acc[2*j+1][0], acc[2*j+1][1], acc[2*j+1][2], acc[2*j+1][3],
                         A.x, A.y, A.z, A.w, Bv.z, Bv.w);
            }
        }
        #pragma unroll
        for (int j = 0; j < 6; j++) {       // gelu + pack: accum frag pair == fc2 A frag
            int ktg = nh * 12 + p * 6 + j;
            u32 r0 = pkbf(gelu_exact(acc[2*j][0]),   gelu_exact(acc[2*j][1]));
            u32 r1 = pkbf(gelu_exact(acc[2*j][2]),   gelu_exact(acc[2*j][3]));
            u32 r2 = pkbf(gelu_exact(acc[2*j+1][0]), gelu_exact(acc[2*j+1][1]));
            u32 r3 = pkbf(gelu_exact(acc[2*j+1][2]), gelu_exact(acc[2*j+1][3]));
            *(uint4*)(s_h + ((mt * 24 + ktg) * 32 + lane) * 4) = make_uint4(r0, r1, r2, r3);
        }
    }
    __syncthreads();

    // ---- fc2: M=64, N half=64, K=384 ----
    float out[8][4];
    #pragma unroll
    for (int nt = 0; nt < 8; nt++) {
        float2 bv = *(const float2*)(b2 + e * C_ + (nh * 8 + nt) * 8 + tg * 2);
        out[nt][0] = bv.x; out[nt][1] = bv.y; out[nt][2] = bv.x; out[nt][3] = bv.y;
    }
    const u32* w2base = g_w2k + (e * 8 + nh * 4) * 3072 + lane * 4;
    #pragma unroll 2
    for (int kt = 0; kt < 24; kt++) {
        uint4 A = *(const uint4*)(s_h + ((mt * 24 + kt) * 32 + lane) * 4);
        #pragma unroll
        for (int j = 0; j < 4; j++) {
            uint4 Bv = *(const uint4*)(w2base + j * 3072 + kt * 128);
            mma_bf16(out[2*j][0],   out[2*j][1],   out[2*j][2],   out[2*j][3],
                     A.x, A.y, A.z, A.w, Bv.x, Bv.y);
            mma_bf16(out[2*j+1][0], out[2*j+1][1], out[2*j+1][2], out[2*j+1][3],
                     A.x, A.y, A.z, A.w, Bv.z, Bv.w);
        }
    }
    // ---- epilogue: gate * out -> bf16x2 slot buffer ----
    int m0 = mt * 16 + gg, m1 = m0 + 8;
    float gg0 = s_g[m0], gg1 = s_g[m1];
    u32* o0 = g_obufh + (size_t)(e * N_ + start + m0) * 64;
    u32* o1 = g_obufh + (size_t)(e * N_ + start + m1) * 64;
    #pragma unroll
    for (int nt = 0; nt < 8; nt++) {
        int cp = (nh * 8 + nt) * 4 + tg;
        o0[cp] = pkbf(gg0 * out[nt][0], gg0 * out[nt][1]);
        o1[cp] = pkbf(gg1 * out[nt][2], gg1 * out[nt][3]);
    }
}

// ------------------- K5: combine slots + residual, NCHW -------------------
__global__ void __launch_bounds__(256) k_combine(const float* __restrict__ x,
                                                 float* __restrict__ dout) {
    __shared__ float s_y[C_ * 66];
    __shared__ int s_sl[128];
    int t = threadIdx.x;
    int n0 = blockIdx.x * 64;
    int b = n0 / HW_; int hw0 = n0 % HW_;
    if (t < 128) s_sl[t] = g_slot[n0 * 2 + t];
    __syncthreads();
    #pragma unroll
    for (int i = 0; i < 16; i++) {
        int idx = t + i * 256; int ts = idx >> 6, cp = idx & 63, c = cp * 2;
        int s0 = s_sl[ts * 2], s1 = s_sl[ts * 2 + 1];
        float2 a = upbf(g_obufh[(size_t)s0 * 64 + cp]);
        float2 bb = upbf(g_obufh[(size_t)s1 * 64 + cp]);
        s_y[c * 66 + ts]       = a.x + bb.x;
        s_y[(c + 1) * 66 + ts] = a.y + bb.y;
    }
    __syncthreads();
    size_t base = (size_t)b * C_ * HW_ + hw0;
    #pragma unroll
    for (int i = 0; i < 16; i++) {       // 128 c x 32 float2
        int lin = t + i * 256; int c = lin >> 5, k = lin & 31;
        size_t idx = base + (size_t)c * HW_ + 2 * k;
        float2 xv = *(const float2*)(x + idx);
        float2 yv = *(const float2*)(s_y + c * 66 + 2 * k);
        *(float2*)(dout + idx) = make_float2(yv.x + xv.x, yv.y + xv.y);
    }
}

// ------------------------------- K6: aux loss -------------------------------
__global__ void k_loss(float* __restrict__ dout, int has_loss) {
    __shared__ float s_imp[E_];
    int t = threadIdx.x;
    int e = t >> 5, lane = t & 31;
    if (t < 128) {
        int cnt = g_cnt[e];
        float s = 0.f;
        for (int i = lane; i < cnt; i += 32) s += g_gate[e * N_ + i];
        #pragma unroll
        for (int o = 16; o > 0; o >>= 1) s += __shfl_xor_sync(0xffffffff, s, o);
        if (lane == 0) s_imp[e] = s;
    }
    __syncthreads();
    if (t == 0 && has_loss) {
        float L[E_], I[E_];
        float mi = 0.f, ml = 0.f;
        for (int k = 0; k < E_; k++) {
            I[k] = s_imp[k]; L[k] = (float)g_cnt[k];
            mi += I[k]; ml += L[k];
        }
        mi *= 0.25f; ml *= 0.25f;
        float vi = 0.f, vl = 0.f;
        for (int k = 0; k < E_; k++) {
            float di = I[k] - mi, dl = L[k] - ml;
            vi += di * di; vl += dl * dl;
        }
        vi *= 0.25f; vl *= 0.25f;
        float loss = 1e-2f * (vi / (mi * mi + 1e-10f) + vl / (ml * ml + 1e-10f));
        dout[NCHW_] = loss;
    }
}

// --------------------------------- launcher ---------------------------------
extern "C" void kernel_launch(void* const* d_in, const int* in_sizes, int n_in,
                              void* d_out, int out_size) {
    const float* x      = (const float*)d_in[0];
    const float* prompt = (const float*)d_in[1];
    const float* w_lin  = (const float*)d_in[2];
    const float* b_lin  = (const float*)d_in[3];
    const float* w_conv = (const float*)d_in[4];
    const float* w_gate = (const float*)d_in[5];
    const float* w1     = (const float*)d_in[6];
    const float* b1     = (const float*)d_in[7];
    const float* w2     = (const float*)d_in[8];
    const float* b2     = (const float*)d_in[9];
    float* out = (float*)d_out;

    cudaFuncSetAttribute(k_expert, cudaFuncAttributeMaxDynamicSharedMemorySize, SMX_BYTES);
    cudaFuncSetAttribute(k_conv_gate, cudaFuncAttributeMaxDynamicSharedMemorySize, CV_BYTES);

    k_mean1<<<1024, 256>>>(x);
    k_prep<<<1, 256>>>(prompt, w_lin, b_lin, w_conv);
    int packn = 196608 + E_ * HIDP_ + 16384;
    k_pack<<<(packn + 255) / 256, 256>>>(w1, b1, w2);
    k_conv_gate<<<N_ / 64, 256, CV_BYTES>>>(x, w_gate);
    dim3 ge(N_ / 64, E_);
    k_expert<<<ge, 256, SMX_BYTES>>>(b2);
    k_combine<<<N_ / 64, 256>>>(x, out);
    k_loss<<<1, 128>>>(out, (out_size > NCHW_) ? 1 : 0);
}